// round 16
// baseline (speedup 1.0000x reference)
#include <cuda_runtime.h>
#include <cuda_bf16.h>
#include <cstdint>
#include <cstddef>

#define BB   512
#define SSC  1024
#define HHD  256
#define PIN  512
#define INDIM 19

#define MIMO_OFF (BB*SSC)
#define ATT_OFF  (MIMO_OFF + BB*8)
#define RAD_OFF  (ATT_OFF + BB*HHD)

// ---------------- device scratch ----------------
__device__ __align__(256) float g_x[BB*INDIM];
__device__ __align__(256) float g_h0[2][BB*HHD];
__device__ __align__(256) float g_h1[2][BB*HHD];
__device__ __align__(256) float g_c[BB*2*HHD];

// ---------------- f32x2 helpers (MLP chain) ----------------
__device__ __forceinline__ unsigned long long splat2(float a) {
    unsigned long long r; asm("mov.b64 %0, {%1, %1};" : "=l"(r) : "f"(a)); return r;
}
__device__ __forceinline__ void ffma2(unsigned long long& d, unsigned long long a, unsigned long long b) {
    asm("fma.rn.f32x2 %0, %1, %2, %3;" : "=l"(d) : "l"(a), "l"(b), "l"(d));
}
__device__ __forceinline__ float2 unpack2(unsigned long long v) {
    float2 r; asm("mov.b64 {%0, %1}, %2;" : "=f"(r.x), "=f"(r.y) : "l"(v)); return r;
}

// ---------------- warp MMA helpers (baseline PTX, sm_80+) ----------------
__device__ __forceinline__ uint32_t s2u(const void* p) {
    uint32_t a;
    asm("{ .reg .u64 t; cvta.to.shared.u64 t, %1; cvt.u32.u64 %0, t; }" : "=r"(a) : "l"(p));
    return a;
}
__device__ __forceinline__ void ldsm4(uint32_t a, uint32_t& r0, uint32_t& r1, uint32_t& r2, uint32_t& r3) {
    asm volatile("ldmatrix.sync.aligned.m8n8.x4.shared.b16 {%0,%1,%2,%3}, [%4];"
        : "=r"(r0), "=r"(r1), "=r"(r2), "=r"(r3) : "r"(a));
}
__device__ __forceinline__ void ldsm2(uint32_t a, uint32_t& r0, uint32_t& r1) {
    asm volatile("ldmatrix.sync.aligned.m8n8.x2.shared.b16 {%0,%1}, [%2];"
        : "=r"(r0), "=r"(r1) : "r"(a));
}
__device__ __forceinline__ void mma16816(float* c,
    uint32_t a0, uint32_t a1, uint32_t a2, uint32_t a3, uint32_t b0, uint32_t b1) {
    asm volatile("mma.sync.aligned.m16n8k16.row.col.f32.bf16.bf16.f32 "
        "{%0,%1,%2,%3}, {%4,%5,%6,%7}, {%8,%9}, {%0,%1,%2,%3};"
        : "+f"(c[0]), "+f"(c[1]), "+f"(c[2]), "+f"(c[3])
        : "r"(a0), "r"(a1), "r"(a2), "r"(a3), "r"(b0), "r"(b1));
}

// fp32x4 -> bf16 hi/lo pairs, stored with per-8-row 16B-chunk XOR swizzle.
// x = byte offset within row (multiple of 8), rowbytes in {128, 512}.
__device__ __forceinline__ void split_store(float4 v, char* hiT, char* loT, int r, int x, int rowbytes) {
    uint32_t h0, h1, l0, l1;
    asm("cvt.rn.bf16x2.f32 %0, %1, %2;" : "=r"(h0) : "f"(v.y), "f"(v.x));
    asm("cvt.rn.bf16x2.f32 %0, %1, %2;" : "=r"(h1) : "f"(v.w), "f"(v.z));
    float r0 = __uint_as_float(h0 << 16);
    float r1 = __uint_as_float(h0 & 0xffff0000u);
    float r2 = __uint_as_float(h1 << 16);
    float r3 = __uint_as_float(h1 & 0xffff0000u);
    asm("cvt.rn.bf16x2.f32 %0, %1, %2;" : "=r"(l0) : "f"(v.y - r1), "f"(v.x - r0));
    asm("cvt.rn.bf16x2.f32 %0, %1, %2;" : "=r"(l1) : "f"(v.w - r3), "f"(v.z - r2));
    int sw = r * rowbytes + (x ^ ((r & 7) << 4));
    *(uint32_t*)(hiT + sw)     = h0;
    *(uint32_t*)(hiT + sw + 4) = h1;
    *(uint32_t*)(loT + sw)     = l0;
    *(uint32_t*)(loT + sw + 4) = l1;
}

// pack one (v0, v1) pair -> hi/lo bf16x2, H1 region (512B rows)
__device__ __forceinline__ void store_pair(char* hiT, char* loT, int r, int x, float v0, float v1) {
    uint32_t h;
    asm("cvt.rn.bf16x2.f32 %0, %1, %2;" : "=r"(h) : "f"(v1), "f"(v0));
    float h0 = __uint_as_float(h << 16);
    float h1 = __uint_as_float(h & 0xffff0000u);
    uint32_t l;
    asm("cvt.rn.bf16x2.f32 %0, %1, %2;" : "=r"(l) : "f"(v1 - h1), "f"(v0 - h0));
    int sw = r * 512 + (x ^ ((r & 7) << 4));
    *(uint32_t*)(hiT + sw) = h;
    *(uint32_t*)(loT + sw) = l;
}

// ---------------- concat ----------------
__global__ void concat_kernel(const float* __restrict__ pos,
                              const float* __restrict__ ue,
                              const float* __restrict__ bsa,
                              const float* __restrict__ extra) {
    int b = threadIdx.x;
    if (b >= BB) return;
    float* x = g_x + b * INDIM;
    x[0] = pos[b*3+0]; x[1] = pos[b*3+1]; x[2] = pos[b*3+2];
    x[3] = ue[b*2+0];  x[4] = ue[b*2+1];
    x[5] = bsa[b*4+0]; x[6] = bsa[b*4+1]; x[7] = bsa[b*4+2]; x[8] = bsa[b*4+3];
    #pragma unroll
    for (int i = 0; i < 10; i++) x[9+i] = extra[b*10+i];
}

// ---------------- MLP chain layer (known-good) ----------------
struct MlpArgs {
    const float* A0; const float* A1;
    const float* W0; const float* W1;
    const float* bi0; const float* bi1;
    float* out0; float* out1;
    float* o20; float* o21;
    int lda, K, ostride, o2stride;
};

__global__ void __launch_bounds__(256) mlp_gemm_relu(MlpArgs p) {
    __shared__ __align__(16) float sA[16*66];
    __shared__ __align__(16) float sB[16*66];

    int net = blockIdx.z;
    const float* A    = net ? p.A1  : p.A0;
    const float* W    = net ? p.W1  : p.W0;
    const float* bias = net ? p.bi1 : p.bi0;
    float* out  = net ? p.out1 : p.out0;
    float* out2 = net ? p.o21  : p.o20;

    int b0 = blockIdx.x * 64, h0 = blockIdx.y * 64;
    int t  = threadIdx.x;
    int tx = t & 15, ty = t >> 4;
    int lr = t >> 2, lq = t & 3;

    unsigned long long acc[4][2];
    #pragma unroll
    for (int i = 0; i < 4; i++) { acc[i][0] = 0ull; acc[i][1] = 0ull; }

    int nkt = (p.K + 15) >> 4;
    for (int kt = 0; kt < nkt; ++kt) {
        int kbase = kt * 16;
        #pragma unroll
        for (int e = 0; e < 4; ++e) {
            int k = kbase + lq*4 + e;
            sA[(lq*4+e)*66 + lr] = (k < p.K) ? A[(size_t)(b0+lr)*p.lda + k] : 0.f;
            sB[(lq*4+e)*66 + lr] = (k < p.K) ? W[(size_t)(h0+lr)*p.K  + k] : 0.f;
        }
        __syncthreads();
        #pragma unroll
        for (int k = 0; k < 16; ++k) {
            unsigned long long bp0 = *(const unsigned long long*)&sB[k*66 + tx*4];
            unsigned long long bp1 = *(const unsigned long long*)&sB[k*66 + tx*4 + 2];
            #pragma unroll
            for (int i = 0; i < 4; ++i) {
                unsigned long long ap = splat2(sA[k*66 + ty*4 + i]);
                ffma2(acc[i][0], ap, bp0);
                ffma2(acc[i][1], ap, bp1);
            }
        }
        __syncthreads();
    }

    float bv[4];
    #pragma unroll
    for (int j = 0; j < 4; j++) bv[j] = bias[h0 + tx*4 + j];

    #pragma unroll
    for (int i = 0; i < 4; ++i) {
        int r = b0 + ty*4 + i;
        float2 v0 = unpack2(acc[i][0]);
        float2 v1 = unpack2(acc[i][1]);
        float o0 = fmaxf(v0.x + bv[0], 0.f);
        float o1 = fmaxf(v0.y + bv[1], 0.f);
        float o2 = fmaxf(v1.x + bv[2], 0.f);
        float o3 = fmaxf(v1.y + bv[3], 0.f);
        float* po = out + (size_t)r * p.ostride + h0 + tx*4;
        po[0] = o0; po[1] = o1; po[2] = o2; po[3] = o3;
        if (out2) {
            float* q = out2 + (size_t)r * p.o2stride + h0 + tx*4;
            q[0] = o0; q[1] = o1; q[2] = o2; q[3] = o3;
        }
    }
}

// ---------------- prism via mma.sync bf16-split ----------------
// smem map (bytes):
//   [0,      65536)  A region: L1 C tiles 2 bufs x (hi16K+lo16K) | L2 W2 (hi32K+lo32K)
//   [65536, 196608)  B region: L1 W1 tiles 2 bufs x (hi32K+lo32K) | L2 H1 (hi64K+lo64K)
//   [196608,199680)  sb1, sb2, sw3
//   [199680,203776)  red[128][8]
#define P_SMEM 203776

// one K=64 chunk of MMAs: 4 k16 steps, warp tile 64x32, 3 split terms
__device__ __forceinline__ void mma_k64(
    float acc[4][4][4],
    uint32_t aHi, uint32_t aLoD, int aStride, int akx0,
    uint32_t bHi, uint32_t bLoD,
    int mi, int ni, int arow_off, int acol16, int brow_off, int bcol16)
{
    uint32_t abase[4]; int axor[4];
    #pragma unroll
    for (int mt = 0; mt < 4; mt++) {
        int r = mi*64 + mt*16 + arow_off;
        abase[mt] = aHi + r * aStride;
        axor[mt]  = (r & 7) << 4;
    }
    uint32_t bbase[4]; int bxor[4];
    #pragma unroll
    for (int nt = 0; nt < 4; nt++) {
        int r = ni*32 + nt*8 + brow_off;
        bbase[nt] = bHi + r * 128;
        bxor[nt]  = (r & 7) << 4;
    }
    #pragma unroll
    for (int ks = 0; ks < 4; ks++) {
        int akx = akx0 + ks*32 + acol16;
        int bkx = ks*32 + bcol16;
        uint32_t bh[4][2], bl[4][2];
        #pragma unroll
        for (int nt = 0; nt < 4; nt++) {
            uint32_t ba = bbase[nt] + (uint32_t)(bkx ^ bxor[nt]);
            ldsm2(ba,        bh[nt][0], bh[nt][1]);
            ldsm2(ba + bLoD, bl[nt][0], bl[nt][1]);
        }
        #pragma unroll
        for (int mt = 0; mt < 4; mt++) {
            uint32_t aa = abase[mt] + (uint32_t)(akx ^ axor[mt]);
            uint32_t ah0, ah1, ah2, ah3, al0, al1, al2, al3;
            ldsm4(aa,        ah0, ah1, ah2, ah3);
            ldsm4(aa + aLoD, al0, al1, al2, al3);
            #pragma unroll
            for (int nt = 0; nt < 4; nt++) {
                mma16816(acc[mt][nt], ah0, ah1, ah2, ah3, bh[nt][0], bh[nt][1]);
                mma16816(acc[mt][nt], ah0, ah1, ah2, ah3, bl[nt][0], bl[nt][1]);
                mma16816(acc[mt][nt], al0, al1, al2, al3, bh[nt][0], bh[nt][1]);
            }
        }
    }
}

__global__ void __launch_bounds__(512, 1) prism_mma(
    const float* __restrict__ pw1, const float* __restrict__ pb1,
    const float* __restrict__ pw2, const float* __restrict__ pb2,
    const float* __restrict__ pw3, const float* __restrict__ pb3,
    float* __restrict__ out_sub)
{
    extern __shared__ char smc[];
    const int t    = threadIdx.x;
    const int lane = t & 31;
    const int wid  = t >> 5;
    const int mi   = wid >> 3;   // 0..1
    const int ni   = wid & 7;    // 0..7
    const int s    = blockIdx.y;
    const int b0   = blockIdx.x * 128;

    char* Areg = smc;
    char* Breg = smc + 65536;
    float* sb1 = (float*)(smc + 196608);
    float* sb2 = sb1 + 256;
    float* sw3 = sb2 + 256;
    float* red = sw3 + 256;      // [128][8]

    const uint32_t uA = s2u(Areg);
    const uint32_t uB = s2u(Breg);

    if (t < 256) {
        sb1[t] = pb1[(size_t)s*HHD + t];
        sb2[t] = pb2[(size_t)s*HHD + t];
        sw3[t] = pw3[(size_t)s*HHD + t];
    }

    const float* w1s = pw1 + (size_t)s * (HHD*PIN);
    const float* w2s = pw2 + (size_t)s * (HHD*HHD);
    const float* Cb  = g_c + (size_t)b0 * PIN;

    // ldmatrix lane geometry
    const int arow_off = (lane & 7) + ((lane >> 3) & 1) * 8;
    const int acol16   = (lane >> 4) * 16;
    const int ln16     = lane & 15;
    const int brow_off = ln16 & 7;
    const int bcol16   = (ln16 >> 3) * 16;

    // conversion lane geometry
    const int cr = t >> 2, cq = t & 3;   // C: row, quarter (16 elems)
    const int wr = t >> 1, wh = t & 1;   // W: row, half (32 elems)

    float acc[4][4][4];
    #pragma unroll
    for (int a = 0; a < 4; a++)
        #pragma unroll
        for (int b = 0; b < 4; b++)
            #pragma unroll
            for (int c = 0; c < 4; c++) acc[a][b][c] = 0.f;

    // ======== Layer 1: acc = C[128,512] @ W1^T ========
    {   // chunk 0 into buf 0
        const float* src = Cb + (size_t)cr * PIN + cq*16;
        #pragma unroll
        for (int e = 0; e < 4; e++)
            split_store(*(const float4*)(src + e*4), Areg, Areg + 16384, cr, cq*32 + e*8, 128);
        const float* ws = w1s + (size_t)wr * PIN + wh*32;
        #pragma unroll
        for (int e = 0; e < 8; e++)
            split_store(*(const float4*)(ws + e*4), Breg, Breg + 32768, wr, wh*64 + e*8, 128);
    }
    __syncthreads();

    for (int i = 0; i < 8; ++i) {
        int p = i & 1;
        mma_k64(acc, uA + p*32768, 16384, 128, 0, uB + p*65536, 32768,
                mi, ni, arow_off, acol16, brow_off, bcol16);
        if (i < 7) {
            __syncthreads();
            int q = p ^ 1;
            const float* src = Cb + (size_t)cr * PIN + (i+1)*64 + cq*16;
            #pragma unroll
            for (int e = 0; e < 4; e++)
                split_store(*(const float4*)(src + e*4),
                            Areg + q*32768, Areg + q*32768 + 16384, cr, cq*32 + e*8, 128);
            const float* ws = w1s + (size_t)wr * PIN + (i+1)*64 + wh*32;
            #pragma unroll
            for (int e = 0; e < 8; e++)
                split_store(*(const float4*)(ws + e*4),
                            Breg + q*65536, Breg + q*65536 + 32768, wr, wh*64 + e*8, 128);
            __syncthreads();
        }
    }
    __syncthreads();

    // ======== H1 = relu(acc + b1) -> bf16 hi/lo into B region (512B rows) ========
    {
        const int qr   = lane >> 2;
        const int col0 = ni*32 + 2*(lane & 3);
        #pragma unroll
        for (int mt = 0; mt < 4; mt++) {
            int r0 = mi*64 + mt*16 + qr;
            #pragma unroll
            for (int nt = 0; nt < 4; nt++) {
                int col = col0 + nt*8;
                float* a = acc[mt][nt];
                float v00 = fmaxf(a[0] + sb1[col],   0.f);
                float v01 = fmaxf(a[1] + sb1[col+1], 0.f);
                float v10 = fmaxf(a[2] + sb1[col],   0.f);
                float v11 = fmaxf(a[3] + sb1[col+1], 0.f);
                store_pair(Breg, Breg + 65536, r0,     col*2, v00, v01);
                store_pair(Breg, Breg + 65536, r0 + 8, col*2, v10, v11);
                a[0] = a[1] = a[2] = a[3] = 0.f;
            }
        }
    }
    __syncthreads();

    // ======== Layer 2: acc = H1[128,256] @ W2^T ========
    for (int j = 0; j < 4; ++j) {
        const float* ws = w2s + (size_t)wr * HHD + j*64 + wh*32;
        #pragma unroll
        for (int e = 0; e < 8; e++)
            split_store(*(const float4*)(ws + e*4), Areg, Areg + 32768, wr, wh*64 + e*8, 128);
        __syncthreads();
        mma_k64(acc, uB, 65536, 512, j*128, uA, 32768,
                mi, ni, arow_off, acol16, brow_off, bcol16);
        __syncthreads();
    }

    // ======== epilogue: sub[r] = sum_o relu(acc + b2[o]) * w3[o] + b3 ========
    {
        const int qr   = lane >> 2;
        const int col0 = ni*32 + 2*(lane & 3);
        #pragma unroll
        for (int mt = 0; mt < 4; mt++) {
            float p0 = 0.f, p1 = 0.f;
            #pragma unroll
            for (int nt = 0; nt < 4; nt++) {
                int col = col0 + nt*8;
                float* a = acc[mt][nt];
                p0 += fmaxf(a[0] + sb2[col],   0.f) * sw3[col]
                    + fmaxf(a[1] + sb2[col+1], 0.f) * sw3[col+1];
                p1 += fmaxf(a[2] + sb2[col],   0.f) * sw3[col]
                    + fmaxf(a[3] + sb2[col+1], 0.f) * sw3[col+1];
            }
            p0 += __shfl_xor_sync(0xffffffffu, p0, 1);
            p0 += __shfl_xor_sync(0xffffffffu, p0, 2);
            p1 += __shfl_xor_sync(0xffffffffu, p1, 1);
            p1 += __shfl_xor_sync(0xffffffffu, p1, 2);
            if ((lane & 3) == 0) {
                int r0 = mi*64 + mt*16 + qr;
                red[r0*8 + ni]       = p0;
                red[(r0 + 8)*8 + ni] = p1;
            }
        }
    }
    __syncthreads();
    if (t < 128) {
        float sum = pb3[s];
        #pragma unroll
        for (int w = 0; w < 8; w++) sum += red[t*8 + w];
        out_sub[(size_t)(b0 + t) * SSC + s] = sum;
    }
}

// ---------------- mimo ----------------
__global__ void __launch_bounds__(256) mimo_kernel(
    const float* __restrict__ sub, const float* __restrict__ mw,
    const float* __restrict__ mb, float* __restrict__ out)
{
    int b = blockIdx.x;
    __shared__ float srow[SSC];
    int t = threadIdx.x;
    for (int i = t; i < SSC; i += 256) srow[i] = sub[(size_t)b*SSC + i];
    __syncthreads();
    int w = t >> 5, lane = t & 31;
    float sum = 0.f;
    for (int i = lane; i < SSC; i += 32) sum += srow[i] * mw[(size_t)w*SSC + i];
    #pragma unroll
    for (int off = 16; off; off >>= 1) sum += __shfl_xor_sync(0xffffffffu, sum, off);
    if (lane == 0) out[b*8 + w] = sum + mb[w];
}

// ---------------- launch ----------------
extern "C" void kernel_launch(void* const* d_in, const int* in_sizes, int n_in,
                              void* d_out, int out_size) {
    const float* positions = (const float*)d_in[0];
    const float* ue        = (const float*)d_in[1];
    const float* bsa       = (const float*)d_in[2];
    const float* extra     = (const float*)d_in[3];
    const float* att_w0    = (const float*)d_in[4];
    const float* att_b0    = (const float*)d_in[5];
    const float* att_wr    = (const float*)d_in[6];
    const float* att_br    = (const float*)d_in[7];
    const float* rad_w0    = (const float*)d_in[8];
    const float* rad_b0    = (const float*)d_in[9];
    const float* rad_wr    = (const float*)d_in[10];
    const float* rad_br    = (const float*)d_in[11];
    const float* p_w1      = (const float*)d_in[12];
    const float* p_b1      = (const float*)d_in[13];
    const float* p_w2      = (const float*)d_in[14];
    const float* p_b2      = (const float*)d_in[15];
    const float* p_w3      = (const float*)d_in[16];
    const float* p_b3      = (const float*)d_in[17];
    const float* mimo_w    = (const float*)d_in[18];
    const float* mimo_b    = (const float*)d_in[19];
    float* out = (float*)d_out;

    float *px, *ph0, *ph1, *pc;
    cudaGetSymbolAddress((void**)&px,  g_x);
    cudaGetSymbolAddress((void**)&ph0, g_h0);
    cudaGetSymbolAddress((void**)&ph1, g_h1);
    cudaGetSymbolAddress((void**)&pc,  g_c);
    float* h0n[2] = { ph0, ph0 + BB*HHD };
    float* h1n[2] = { ph1, ph1 + BB*HHD };

    concat_kernel<<<1, 512>>>(positions, ue, bsa, extra);

    dim3 mgrid(8, 4, 2);
    {
        MlpArgs a;
        a.A0 = px; a.A1 = px; a.lda = INDIM; a.K = INDIM;
        a.W0 = att_w0; a.W1 = rad_w0; a.bi0 = att_b0; a.bi1 = rad_b0;
        a.out0 = h0n[0]; a.out1 = h0n[1]; a.ostride = HHD;
        a.o20 = nullptr; a.o21 = nullptr; a.o2stride = 0;
        mlp_gemm_relu<<<mgrid, 256>>>(a);
    }
    for (int l = 1; l <= 7; ++l) {
        MlpArgs a;
        float** inb  = (l & 1) ? h0n : h1n;
        float** outb = (l & 1) ? h1n : h0n;
        a.A0 = inb[0]; a.A1 = inb[1]; a.lda = HHD; a.K = HHD;
        a.W0 = att_wr + (size_t)(l-1)*HHD*HHD;
        a.W1 = rad_wr + (size_t)(l-1)*HHD*HHD;
        a.bi0 = att_br + (size_t)(l-1)*HHD;
        a.bi1 = rad_br + (size_t)(l-1)*HHD;
        if (l < 7) {
            a.out0 = outb[0]; a.out1 = outb[1]; a.ostride = HHD;
            a.o20 = nullptr; a.o21 = nullptr; a.o2stride = 0;
        } else {
            a.out0 = pc; a.out1 = pc + HHD; a.ostride = 2*HHD;
            a.o20 = out + ATT_OFF; a.o21 = out + RAD_OFF; a.o2stride = HHD;
        }
        mlp_gemm_relu<<<mgrid, 256>>>(a);
    }

    cudaFuncSetAttribute(prism_mma,
                         cudaFuncAttributeMaxDynamicSharedMemorySize, P_SMEM);
    prism_mma<<<dim3(4, 1024), 512, P_SMEM>>>(
        p_w1, p_b1, p_w2, p_b2, p_w3, p_b3, out /* sub */);

    mimo_kernel<<<512, 256>>>(out, mimo_w, mimo_b, out + MIMO_OFF);
}

// round 17
// speedup vs baseline: 1.5156x; 1.5156x over previous
#include <cuda_runtime.h>
#include <cuda_fp16.h>
#include <cstdint>
#include <cstddef>

#define BB   512
#define SSC  1024
#define HHD  256
#define PIN  512
#define INDIM 19

#define MIMO_OFF (BB*SSC)
#define ATT_OFF  (MIMO_OFF + BB*8)
#define RAD_OFF  (ATT_OFF + BB*HHD)

// ---------------- device scratch ----------------
__device__ __align__(256) float g_x[BB*INDIM];
__device__ __align__(256) float g_h0[2][BB*HHD];
__device__ __align__(256) float g_h1[2][BB*HHD];
__device__ __align__(256) float g_c[BB*2*HHD];

// ---------------- f32x2 helpers (MLP chain) ----------------
__device__ __forceinline__ unsigned long long splat2(float a) {
    unsigned long long r; asm("mov.b64 %0, {%1, %1};" : "=l"(r) : "f"(a)); return r;
}
__device__ __forceinline__ void ffma2(unsigned long long& d, unsigned long long a, unsigned long long b) {
    asm("fma.rn.f32x2 %0, %1, %2, %3;" : "=l"(d) : "l"(a), "l"(b), "l"(d));
}
__device__ __forceinline__ float2 unpack2(unsigned long long v) {
    float2 r; asm("mov.b64 {%0, %1}, %2;" : "=f"(r.x), "=f"(r.y) : "l"(v)); return r;
}

// ---------------- warp MMA helpers ----------------
__device__ __forceinline__ uint32_t s2u(const void* p) {
    uint32_t a;
    asm("{ .reg .u64 t; cvta.to.shared.u64 t, %1; cvt.u32.u64 %0, t; }" : "=r"(a) : "l"(p));
    return a;
}
__device__ __forceinline__ void ldsm4(uint32_t a, uint32_t& r0, uint32_t& r1, uint32_t& r2, uint32_t& r3) {
    asm volatile("ldmatrix.sync.aligned.m8n8.x4.shared.b16 {%0,%1,%2,%3}, [%4];"
        : "=r"(r0), "=r"(r1), "=r"(r2), "=r"(r3) : "r"(a));
}
__device__ __forceinline__ void mma16816h(float* c,
    uint32_t a0, uint32_t a1, uint32_t a2, uint32_t a3, uint32_t b0, uint32_t b1) {
    asm volatile("mma.sync.aligned.m16n8k16.row.col.f32.f16.f16.f32 "
        "{%0,%1,%2,%3}, {%4,%5,%6,%7}, {%8,%9}, {%0,%1,%2,%3};"
        : "+f"(c[0]), "+f"(c[1]), "+f"(c[2]), "+f"(c[3])
        : "r"(a0), "r"(a1), "r"(a2), "r"(a3), "r"(b0), "r"(b1));
}

// ---------------- fp16 pack/split helpers ----------------
__device__ __forceinline__ void split2(float a, float b, uint32_t& hi, uint32_t& lo) {
    __half2 h = __floats2half2_rn(a, b);
    float2 r = __half22float2(h);
    __half2 l = __floats2half2_rn(a - r.x, b - r.y);
    hi = *reinterpret_cast<uint32_t*>(&h);
    lo = *reinterpret_cast<uint32_t*>(&l);
}
__device__ __forceinline__ uint32_t pack2(float a, float b) {
    __half2 h = __floats2half2_rn(a, b);
    return *reinterpret_cast<uint32_t*>(&h);
}

// 16 fp32 -> 16 fp16 hi + 16 fp16 lo, swizzled (128B rows), x multiple of 32
__device__ __forceinline__ void split_store16(const float4* v, char* hiT, char* loT, int r, int x) {
    uint32_t h[8], l[8];
    #pragma unroll
    for (int i = 0; i < 4; i++) {
        split2(v[i].x, v[i].y, h[2*i],   l[2*i]);
        split2(v[i].z, v[i].w, h[2*i+1], l[2*i+1]);
    }
    int xr = (r & 7) << 4;
    int sw0 = r*128 + (x ^ xr);
    int sw1 = r*128 + ((x+16) ^ xr);
    *(uint4*)(hiT+sw0) = make_uint4(h[0],h[1],h[2],h[3]);
    *(uint4*)(hiT+sw1) = make_uint4(h[4],h[5],h[6],h[7]);
    *(uint4*)(loT+sw0) = make_uint4(l[0],l[1],l[2],l[3]);
    *(uint4*)(loT+sw1) = make_uint4(l[4],l[5],l[6],l[7]);
}

// 16 fp32 -> 16 fp16 (no split), swizzled (128B rows), x multiple of 32
__device__ __forceinline__ void pack_store16(const float4* v, char* T, int r, int x) {
    uint32_t h[8];
    #pragma unroll
    for (int i = 0; i < 4; i++) {
        h[2*i]   = pack2(v[i].x, v[i].y);
        h[2*i+1] = pack2(v[i].z, v[i].w);
    }
    int xr = (r & 7) << 4;
    int sw0 = r*128 + (x ^ xr);
    int sw1 = r*128 + ((x+16) ^ xr);
    *(uint4*)(T+sw0) = make_uint4(h[0],h[1],h[2],h[3]);
    *(uint4*)(T+sw1) = make_uint4(h[4],h[5],h[6],h[7]);
}

// (v0,v1) pair -> H1 region (512B rows), x = col*2 bytes
__device__ __forceinline__ void store_pair_h(char* hiT, char* loT, int r, int x, float v0, float v1) {
    uint32_t h, l;
    split2(v0, v1, h, l);
    int sw = r*512 + (x ^ ((r & 7) << 4));
    *(uint32_t*)(hiT + sw) = h;
    *(uint32_t*)(loT + sw) = l;
}

// ---------------- concat ----------------
__global__ void concat_kernel(const float* __restrict__ pos,
                              const float* __restrict__ ue,
                              const float* __restrict__ bsa,
                              const float* __restrict__ extra) {
    int b = threadIdx.x;
    if (b >= BB) return;
    float* x = g_x + b * INDIM;
    x[0] = pos[b*3+0]; x[1] = pos[b*3+1]; x[2] = pos[b*3+2];
    x[3] = ue[b*2+0];  x[4] = ue[b*2+1];
    x[5] = bsa[b*4+0]; x[6] = bsa[b*4+1]; x[7] = bsa[b*4+2]; x[8] = bsa[b*4+3];
    #pragma unroll
    for (int i = 0; i < 10; i++) x[9+i] = extra[b*10+i];
}

// ---------------- MLP chain layer (known-good) ----------------
struct MlpArgs {
    const float* A0; const float* A1;
    const float* W0; const float* W1;
    const float* bi0; const float* bi1;
    float* out0; float* out1;
    float* o20; float* o21;
    int lda, K, ostride, o2stride;
};

__global__ void __launch_bounds__(256) mlp_gemm_relu(MlpArgs p) {
    __shared__ __align__(16) float sA[16*66];
    __shared__ __align__(16) float sB[16*66];

    int net = blockIdx.z;
    const float* A    = net ? p.A1  : p.A0;
    const float* W    = net ? p.W1  : p.W0;
    const float* bias = net ? p.bi1 : p.bi0;
    float* out  = net ? p.out1 : p.out0;
    float* out2 = net ? p.o21  : p.o20;

    int b0 = blockIdx.x * 64, h0 = blockIdx.y * 64;
    int t  = threadIdx.x;
    int tx = t & 15, ty = t >> 4;
    int lr = t >> 2, lq = t & 3;

    unsigned long long acc[4][2];
    #pragma unroll
    for (int i = 0; i < 4; i++) { acc[i][0] = 0ull; acc[i][1] = 0ull; }

    int nkt = (p.K + 15) >> 4;
    for (int kt = 0; kt < nkt; ++kt) {
        int kbase = kt * 16;
        #pragma unroll
        for (int e = 0; e < 4; ++e) {
            int k = kbase + lq*4 + e;
            sA[(lq*4+e)*66 + lr] = (k < p.K) ? A[(size_t)(b0+lr)*p.lda + k] : 0.f;
            sB[(lq*4+e)*66 + lr] = (k < p.K) ? W[(size_t)(h0+lr)*p.K  + k] : 0.f;
        }
        __syncthreads();
        #pragma unroll
        for (int k = 0; k < 16; ++k) {
            unsigned long long bp0 = *(const unsigned long long*)&sB[k*66 + tx*4];
            unsigned long long bp1 = *(const unsigned long long*)&sB[k*66 + tx*4 + 2];
            #pragma unroll
            for (int i = 0; i < 4; ++i) {
                unsigned long long ap = splat2(sA[k*66 + ty*4 + i]);
                ffma2(acc[i][0], ap, bp0);
                ffma2(acc[i][1], ap, bp1);
            }
        }
        __syncthreads();
    }

    float bv[4];
    #pragma unroll
    for (int j = 0; j < 4; j++) bv[j] = bias[h0 + tx*4 + j];

    #pragma unroll
    for (int i = 0; i < 4; ++i) {
        int r = b0 + ty*4 + i;
        float2 v0 = unpack2(acc[i][0]);
        float2 v1 = unpack2(acc[i][1]);
        float o0 = fmaxf(v0.x + bv[0], 0.f);
        float o1 = fmaxf(v0.y + bv[1], 0.f);
        float o2 = fmaxf(v1.x + bv[2], 0.f);
        float o3 = fmaxf(v1.y + bv[3], 0.f);
        float* po = out + (size_t)r * p.ostride + h0 + tx*4;
        po[0] = o0; po[1] = o1; po[2] = o2; po[3] = o3;
        if (out2) {
            float* q = out2 + (size_t)r * p.o2stride + h0 + tx*4;
            q[0] = o0; q[1] = o1; q[2] = o2; q[3] = o3;
        }
    }
}

// ---------------- prism: fp16 2-term split via mma.sync ----------------
// smem map:
//   [0, 65536)       L1 C bufs: p*32768 (hi +0, lo +16384)   -> later H1 hi [0,64K)
//   [65536, 131072)  L1 W1 bufs: p*32768 (32KB fp16 each)    -> later H1 lo
//   [131072, 196608) W2 bufs: p*32768 (32KB each)
//   [196608, 199680) sb1, sb2, sw3
//   [199680, 203776) red[128][8]
#define P_SMEM 203776

// one K=64 chunk: 4 k16 steps, warp tile 64x32, 2 split terms (A hi/lo, B single)
__device__ __forceinline__ void mma_k64_2t(
    float acc[4][4][4],
    uint32_t aBase, uint32_t aLoD, int aStride, int akx0,
    uint32_t bBase,
    int mi, int ni, int arow, int acol16, int b_row, int b_c16, int lxor)
{
    #pragma unroll
    for (int ks = 0; ks < 4; ks++) {
        int akx = akx0 + ks*32 + acol16;
        int bkx = ks*32 + b_c16;
        uint32_t b[4][2];
        #pragma unroll
        for (int g = 0; g < 2; g++) {
            uint32_t ba = bBase + (uint32_t)((ni*32 + g*16 + b_row) * 128 + (bkx ^ lxor));
            ldsm4(ba, b[2*g][0], b[2*g][1], b[2*g+1][0], b[2*g+1][1]);
        }
        #pragma unroll
        for (int mt = 0; mt < 4; mt++) {
            uint32_t aa = aBase + (uint32_t)((mi*64 + mt*16 + arow) * aStride + (akx ^ lxor));
            uint32_t ah0, ah1, ah2, ah3, al0, al1, al2, al3;
            ldsm4(aa,        ah0, ah1, ah2, ah3);
            ldsm4(aa + aLoD, al0, al1, al2, al3);
            #pragma unroll
            for (int nt = 0; nt < 4; nt++) {
                mma16816h(acc[mt][nt], ah0, ah1, ah2, ah3, b[nt][0], b[nt][1]);
                mma16816h(acc[mt][nt], al0, al1, al2, al3, b[nt][0], b[nt][1]);
            }
        }
    }
}

__global__ void __launch_bounds__(512, 1) prism_mma(
    const float* __restrict__ pw1, const float* __restrict__ pb1,
    const float* __restrict__ pw2, const float* __restrict__ pb2,
    const float* __restrict__ pw3, const float* __restrict__ pb3,
    float* __restrict__ out_sub)
{
    extern __shared__ char smc[];
    const int t    = threadIdx.x;
    const int lane = t & 31;
    const int wid  = t >> 5;
    const int mi   = wid >> 3;   // 0..1
    const int ni   = wid & 7;    // 0..7
    const int s    = blockIdx.y;
    const int b0   = blockIdx.x * 128;

    char* Cbuf = smc;                 // L1 C tiles / H1 hi
    char* Wbuf = smc + 65536;         // L1 W tiles / H1 lo
    char* W2b  = smc + 131072;
    float* sb1 = (float*)(smc + 196608);
    float* sb2 = sb1 + 256;
    float* sw3 = sb2 + 256;
    float* red = sw3 + 256;           // [128][8]

    const uint32_t uS = s2u(smc);

    if (t < 256) {
        sb1[t] = pb1[(size_t)s*HHD + t];
        sb2[t] = pb2[(size_t)s*HHD + t];
        sw3[t] = pw3[(size_t)s*HHD + t];
    }

    const float* w1s = pw1 + (size_t)s * (HHD*PIN);
    const float* w2s = pw2 + (size_t)s * (HHD*HHD);
    const float* Cb  = g_c + (size_t)b0 * PIN;

    // ldmatrix lane geometry
    const int arow   = lane & 15;
    const int acol16 = (lane >> 4) * 16;
    const int b_row  = ((lane >> 4)) * 8 + (lane & 7);
    const int b_c16  = ((lane >> 3) & 1) * 16;
    const int lxor   = (lane & 7) << 4;

    // staging lane geometry
    const int cr = t >> 2, cq = t & 3;   // C: row 0..127, quarter (16 cols)
    const int wr = t >> 1, wh = t & 1;   // W: row 0..255, half (32 cols)

    float acc[4][4][4];
    #pragma unroll
    for (int a = 0; a < 4; a++)
        #pragma unroll
        for (int b = 0; b < 4; b++)
            #pragma unroll
            for (int c = 0; c < 4; c++) acc[a][b][c] = 0.f;

    // ---- prologue: stage chunk 0, prefetch C chunk 1 ----
    {
        float4 cv[4];
        const float* src = Cb + (size_t)cr * PIN + cq*16;
        #pragma unroll
        for (int e = 0; e < 4; e++) cv[e] = *(const float4*)(src + e*4);
        split_store16(cv, Cbuf, Cbuf + 16384, cr, cq*32);

        const float* ws = w1s + (size_t)wr * PIN + wh*32;
        float4 wv[4];
        #pragma unroll
        for (int e = 0; e < 4; e++) wv[e] = *(const float4*)(ws + e*4);
        pack_store16(wv, Wbuf, wr, wh*64);
        #pragma unroll
        for (int e = 0; e < 4; e++) wv[e] = *(const float4*)(ws + 16 + e*4);
        pack_store16(wv, Wbuf, wr, wh*64 + 32);
    }
    float4 cR[4];
    {
        const float* src = Cb + (size_t)cr * PIN + 64 + cq*16;
        #pragma unroll
        for (int e = 0; e < 4; e++) cR[e] = *(const float4*)(src + e*4);
    }
    __syncthreads();

    // ======== Layer 1: acc = C[128,512] @ W1^T ========
    for (int i = 0; i < 8; ++i) {
        int p = i & 1;
        mma_k64_2t(acc, uS + p*32768, 16384, 128, 0, uS + 65536 + p*32768,
                   mi, ni, arow, acol16, b_row, b_c16, lxor);
        if (i < 7) {
            int q = p ^ 1;
            const float* ws = w1s + (size_t)wr * PIN + (i+1)*64 + wh*32;
            float4 w0[4];
            #pragma unroll
            for (int e = 0; e < 4; e++) w0[e] = *(const float4*)(ws + e*4);
            split_store16(cR, Cbuf + q*32768, Cbuf + q*32768 + 16384, cr, cq*32);
            float4 w1v[4];
            #pragma unroll
            for (int e = 0; e < 4; e++) w1v[e] = *(const float4*)(ws + 16 + e*4);
            pack_store16(w0, Wbuf + q*32768, wr, wh*64);
            if (i < 6) {
                const float* src = Cb + (size_t)cr * PIN + (i+2)*64 + cq*16;
                #pragma unroll
                for (int e = 0; e < 4; e++) cR[e] = *(const float4*)(src + e*4);
            }
            pack_store16(w1v, Wbuf + q*32768, wr, wh*64 + 32);
        }
        __syncthreads();
    }

    // ======== H1 = relu(acc + b1) -> fp16 hi/lo (512B rows); stage W2 chunk0 ========
    {
        const int qr   = lane >> 2;
        const int col0 = ni*32 + 2*(lane & 3);
        #pragma unroll
        for (int mt = 0; mt < 4; mt++) {
            int r0 = mi*64 + mt*16 + qr;
            #pragma unroll
            for (int nt = 0; nt < 4; nt++) {
                int col = col0 + nt*8;
                float* a = acc[mt][nt];
                float v00 = fmaxf(a[0] + sb1[col],   0.f);
                float v01 = fmaxf(a[1] + sb1[col+1], 0.f);
                float v10 = fmaxf(a[2] + sb1[col],   0.f);
                float v11 = fmaxf(a[3] + sb1[col+1], 0.f);
                store_pair_h(Cbuf, Wbuf, r0,     col*2, v00, v01);
                store_pair_h(Cbuf, Wbuf, r0 + 8, col*2, v10, v11);
                a[0] = a[1] = a[2] = a[3] = 0.f;
            }
        }
        const float* ws = w2s + (size_t)wr * HHD + wh*32;
        float4 wv[4];
        #pragma unroll
        for (int e = 0; e < 4; e++) wv[e] = *(const float4*)(ws + e*4);
        pack_store16(wv, W2b, wr, wh*64);
        #pragma unroll
        for (int e = 0; e < 4; e++) wv[e] = *(const float4*)(ws + 16 + e*4);
        pack_store16(wv, W2b, wr, wh*64 + 32);
    }
    __syncthreads();

    // ======== Layer 2: acc = H1[128,256] @ W2^T ========
    for (int j = 0; j < 4; ++j) {
        int p = j & 1;
        mma_k64_2t(acc, uS, 65536, 512, j*128, uS + 131072 + p*32768,
                   mi, ni, arow, acol16, b_row, b_c16, lxor);
        if (j < 3) {
            int q = p ^ 1;
            const float* ws = w2s + (size_t)wr * HHD + (j+1)*64 + wh*32;
            float4 wv[4];
            #pragma unroll
            for (int e = 0; e < 4; e++) wv[e] = *(const float4*)(ws + e*4);
            pack_store16(wv, W2b + q*32768, wr, wh*64);
            #pragma unroll
            for (int e = 0; e < 4; e++) wv[e] = *(const float4*)(ws + 16 + e*4);
            pack_store16(wv, W2b + q*32768, wr, wh*64 + 32);
        }
        __syncthreads();
    }

    // ======== epilogue: sub[r] = sum_o relu(acc + b2[o]) * w3[o] + b3 ========
    {
        const int qr   = lane >> 2;
        const int col0 = ni*32 + 2*(lane & 3);
        #pragma unroll
        for (int mt = 0; mt < 4; mt++) {
            float p0 = 0.f, p1 = 0.f;
            #pragma unroll
            for (int nt = 0; nt < 4; nt++) {
                int col = col0 + nt*8;
                float* a = acc[mt][nt];
                p0 += fmaxf(a[0] + sb2[col],   0.f) * sw3[col]
                    + fmaxf(a[1] + sb2[col+1], 0.f) * sw3[col+1];
                p1 += fmaxf(a[2] + sb2[col],   0.f) * sw3[col]
                    + fmaxf(a[3] + sb2[col+1], 0.f) * sw3[col+1];
            }
            p0 += __shfl_xor_sync(0xffffffffu, p0, 1);
            p0 += __shfl_xor_sync(0xffffffffu, p0, 2);
            p1 += __shfl_xor_sync(0xffffffffu, p1, 1);
            p1 += __shfl_xor_sync(0xffffffffu, p1, 2);
            if ((lane & 3) == 0) {
                int r0 = mi*64 + mt*16 + qr;
                red[r0*8 + ni]       = p0;
                red[(r0 + 8)*8 + ni] = p1;
            }
        }
    }
    __syncthreads();
    if (t < 128) {
        float sum = pb3[s];
        #pragma unroll
        for (int w = 0; w < 8; w++) sum += red[t*8 + w];
        out_sub[(size_t)(b0 + t) * SSC + s] = sum;
    }
}

// ---------------- mimo ----------------
__global__ void __launch_bounds__(256) mimo_kernel(
    const float* __restrict__ sub, const float* __restrict__ mw,
    const float* __restrict__ mb, float* __restrict__ out)
{
    int b = blockIdx.x;
    __shared__ float srow[SSC];
    int t = threadIdx.x;
    for (int i = t; i < SSC; i += 256) srow[i] = sub[(size_t)b*SSC + i];
    __syncthreads();
    int w = t >> 5, lane = t & 31;
    float sum = 0.f;
    for (int i = lane; i < SSC; i += 32) sum += srow[i] * mw[(size_t)w*SSC + i];
    #pragma unroll
    for (int off = 16; off; off >>= 1) sum += __shfl_xor_sync(0xffffffffu, sum, off);
    if (lane == 0) out[b*8 + w] = sum + mb[w];
}

// ---------------- launch ----------------
extern "C" void kernel_launch(void* const* d_in, const int* in_sizes, int n_in,
                              void* d_out, int out_size) {
    const float* positions = (const float*)d_in[0];
    const float* ue        = (const float*)d_in[1];
    const float* bsa       = (const float*)d_in[2];
    const float* extra     = (const float*)d_in[3];
    const float* att_w0    = (const float*)d_in[4];
    const float* att_b0    = (const float*)d_in[5];
    const float* att_wr    = (const float*)d_in[6];
    const float* att_br    = (const float*)d_in[7];
    const float* rad_w0    = (const float*)d_in[8];
    const float* rad_b0    = (const float*)d_in[9];
    const float* rad_wr    = (const float*)d_in[10];
    const float* rad_br    = (const float*)d_in[11];
    const float* p_w1      = (const float*)d_in[12];
    const float* p_b1      = (const float*)d_in[13];
    const float* p_w2      = (const float*)d_in[14];
    const float* p_b2      = (const float*)d_in[15];
    const float* p_w3      = (const float*)d_in[16];
    const float* p_b3      = (const float*)d_in[17];
    const float* mimo_w    = (const float*)d_in[18];
    const float* mimo_b    = (const float*)d_in[19];
    float* out = (float*)d_out;

    float *px, *ph0, *ph1, *pc;
    cudaGetSymbolAddress((void**)&px,  g_x);
    cudaGetSymbolAddress((void**)&ph0, g_h0);
    cudaGetSymbolAddress((void**)&ph1, g_h1);
    cudaGetSymbolAddress((void**)&pc,  g_c);
    float* h0n[2] = { ph0, ph0 + BB*HHD };
    float* h1n[2] = { ph1, ph1 + BB*HHD };

    concat_kernel<<<1, 512>>>(positions, ue, bsa, extra);

    dim3 mgrid(8, 4, 2);
    {
        MlpArgs a;
        a.A0 = px; a.A1 = px; a.lda = INDIM; a.K = INDIM;
        a.W0 = att_w0; a.W1 = rad_w0; a.bi0 = att_b0; a.bi1 = rad_b0;
        a.out0 = h0n[0]; a.out1 = h0n[1]; a.ostride = HHD;
        a.o20 = nullptr; a.o21 = nullptr; a.o2stride = 0;
        mlp_gemm_relu<<<mgrid, 256>>>(a);
    }
    for (int l = 1; l <= 7; ++l) {
        MlpArgs a;
        float** inb  = (l & 1) ? h0n : h1n;
        float** outb = (l & 1) ? h1n : h0n;
        a.A0 = inb[0]; a.A1 = inb[1]; a.lda = HHD; a.K = HHD;
        a.W0 = att_wr + (size_t)(l-1)*HHD*HHD;
        a.W1 = rad_wr + (size_t)(l-1)*HHD*HHD;
        a.bi0 = att_br + (size_t)(l-1)*HHD;
        a.bi1 = rad_br + (size_t)(l-1)*HHD;
        if (l < 7) {
            a.out0 = outb[0]; a.out1 = outb[1]; a.ostride = HHD;
            a.o20 = nullptr; a.o21 = nullptr; a.o2stride = 0;
        } else {
            a.out0 = pc; a.out1 = pc + HHD; a.ostride = 2*HHD;
            a.o20 = out + ATT_OFF; a.o21 = out + RAD_OFF; a.o2stride = HHD;
        }
        mlp_gemm_relu<<<mgrid, 256>>>(a);
    }

    cudaFuncSetAttribute(prism_mma,
                         cudaFuncAttributeMaxDynamicSharedMemorySize, P_SMEM);
    prism_mma<<<dim3(4, 1024), 512, P_SMEM>>>(
        p_w1, p_b1, p_w2, p_b2, p_w3, p_b3, out /* sub */);

    mimo_kernel<<<512, 256>>>(out, mimo_w, mimo_b, out + MIMO_OFF);
}